// round 8
// baseline (speedup 1.0000x reference)
#include <cuda_runtime.h>
#include <cuda_bf16.h>

// GaussianModel: cov = (R*diag(s)) (R*diag(s))^T per Gaussian, N=4M.
// Inputs: rotation_raw float32 [N,4], scaling_raw float32 [N,3]
// Output: cov float32 [N,3,3]
//
// R7: latency/overlap-limited at DRAM=62% (no pipe saturated). Changes:
//  - 2 elements/thread (interleaved i, i+256): half the blocks & barriers,
//    2x front-batched LDG MLP, all global accesses stay contiguous float4.
//  - Guardless main kernel (512-elem blocks), tiny guarded tail kernel.
//  - __ldcs/__stcs streaming hints (touch-once data, evict-first).

__device__ __forceinline__ void cov_one(float4 q, float a0, float a1, float a2,
                                        float* __restrict__ o /* 9 floats */)
{
    float w = q.x, x = q.y, y = q.z, z = q.w;

    // R is quadratic in the normalized quaternion: fold 2/||q||^2 into the
    // cross terms instead of normalizing.
    float n2   = w*w + x*x + y*y + z*z;
    float inv2 = __fdividef(2.0f, n2);

    float xx = x*x*inv2, yy = y*y*inv2, zz = z*z*inv2;
    float xy = x*y*inv2, xz = x*z*inv2, yz = y*z*inv2;
    float wx = w*x*inv2, wy = w*y*inv2, wz = w*z*inv2;

    float r00 = 1.0f - yy - zz, r01 = xy - wz,        r02 = xz + wy;
    float r10 = xy + wz,        r11 = 1.0f - xx - zz, r12 = yz - wx;
    float r20 = xz - wy,        r21 = yz + wx,        r22 = 1.0f - xx - yy;

    // s_k^2 = exp(2 * raw_k)
    float s00 = __expf(2.0f * a0);
    float s11 = __expf(2.0f * a1);
    float s22 = __expf(2.0f * a2);

    float c00 = r00*r00*s00 + r01*r01*s11 + r02*r02*s22;
    float c01 = r00*r10*s00 + r01*r11*s11 + r02*r12*s22;
    float c02 = r00*r20*s00 + r01*r21*s11 + r02*r22*s22;
    float c11 = r10*r10*s00 + r11*r11*s11 + r12*r12*s22;
    float c12 = r10*r20*s00 + r11*r21*s11 + r12*r22*s22;
    float c22 = r20*r20*s00 + r21*r21*s11 + r22*r22*s22;

    // STS.32 stride-9: gcd(9,32)=1 -> conflict-free
    o[0] = c00; o[1] = c01; o[2] = c02;
    o[3] = c01; o[4] = c11; o[5] = c12;
    o[6] = c02; o[7] = c12; o[8] = c22;
}

// Guardless main kernel: each block handles exactly 512 elements.
__global__ __launch_bounds__(256)
void gaussian_cov_main(const float4* __restrict__ rot,
                       const float*  __restrict__ sc,
                       float*        __restrict__ out)
{
    __shared__ float sh_s[512 * 3];   //  6 KB staged scaling
    __shared__ float sh_o[512 * 9];   // 18 KB staged covariance

    const int tid  = threadIdx.x;
    const int base = blockIdx.x * 512;

    // ---- Front-batch all global reads (max MLP before first dependency) ----
    // Quats for elements base+tid and base+tid+256: contiguous LDG.128.
    float4 q0 = __ldcs(&rot[base + tid]);
    float4 q1 = __ldcs(&rot[base + tid + 256]);

    // Stage scaling: 1536 floats = 384 float4, contiguous (3*base % 4 == 0).
    {
        const float4* s4 = (const float4*)(sc + 3 * base);
        float4* sh4 = (float4*)sh_s;
        sh4[tid] = __ldcs(&s4[tid]);
        if (tid < 128) sh4[tid + 256] = __ldcs(&s4[tid + 256]);
    }
    __syncthreads();

    // ---- Compute both elements ----
    {
        int l = tid;                            // local element 0
        cov_one(q0, sh_s[3*l], sh_s[3*l+1], sh_s[3*l+2], sh_o + 9*l);
        l = tid + 256;                          // local element 1
        cov_one(q1, sh_s[3*l], sh_s[3*l+1], sh_s[3*l+2], sh_o + 9*l);
    }
    __syncthreads();

    // ---- Cooperative float4 store: 4608 floats = 1152 float4 ----
    {
        float4* dst = (float4*)(out + 9 * base);     // 9*base % 4 == 0
        const float4* src = (const float4*)sh_o;
        #pragma unroll
        for (int k = 0; k < 4; k++)
            __stcs(&dst[tid + 256 * k], src[tid + 256 * k]);
        if (tid < 128)
            __stcs(&dst[tid + 1024], src[tid + 1024]);
    }
}

// Guarded tail kernel: scalar path for the last (n % 512) elements.
__global__ __launch_bounds__(256)
void gaussian_cov_tail(const float4* __restrict__ rot,
                       const float*  __restrict__ sc,
                       float*        __restrict__ out,
                       int start, int n)
{
    int i = start + blockIdx.x * blockDim.x + threadIdx.x;
    if (i >= n) return;

    float4 q = __ldg(&rot[i]);
    float c[9];
    cov_one(q, __ldg(sc + 3*i), __ldg(sc + 3*i + 1), __ldg(sc + 3*i + 2), c);
    float* o = out + 9 * i;
    #pragma unroll
    for (int k = 0; k < 9; k++) o[k] = c[k];
}

extern "C" void kernel_launch(void* const* d_in, const int* in_sizes, int n_in,
                              void* d_out, int out_size)
{
    const float4* rot = (const float4*)d_in[0];   // [N,4] float32
    const float*  sc  = (const float*) d_in[1];   // [N,3] float32
    float*        out = (float*)d_out;            // [N,3,3] float32

    int n  = in_sizes[0] / 4;
    int nb = n / 512;                             // full guardless blocks
    if (nb > 0)
        gaussian_cov_main<<<nb, 256>>>(rot, sc, out);

    int start = nb * 512;
    int rem   = n - start;
    if (rem > 0)
        gaussian_cov_tail<<<(rem + 255) / 256, 256>>>(rot, sc, out, start, n);
}

// round 9
// speedup vs baseline: 1.0428x; 1.0428x over previous
#include <cuda_runtime.h>
#include <cuda_bf16.h>

// GaussianModel: cov = (R*diag(s)) (R*diag(s))^T per Gaussian, N=4M.
// Inputs: rotation_raw float32 [N,4], scaling_raw float32 [N,3]
// Output: cov float32 [N,3,3]
//
// R8: R7's separate tail kernel ran grid=1 serialized (+5us) — merge it back.
// Single kernel, 512 elems/block (2/thread): all full blocks take a guardless
// fast path; only the final partial block runs the guarded variant.

__device__ __forceinline__ void cov_one(float4 q, float a0, float a1, float a2,
                                        float* __restrict__ o /* 9 floats */)
{
    float w = q.x, x = q.y, y = q.z, z = q.w;

    // R is quadratic in the normalized quaternion: fold 2/||q||^2 into the
    // cross terms instead of normalizing.
    float n2   = w*w + x*x + y*y + z*z;
    float inv2 = __fdividef(2.0f, n2);

    float xx = x*x*inv2, yy = y*y*inv2, zz = z*z*inv2;
    float xy = x*y*inv2, xz = x*z*inv2, yz = y*z*inv2;
    float wx = w*x*inv2, wy = w*y*inv2, wz = w*z*inv2;

    float r00 = 1.0f - yy - zz, r01 = xy - wz,        r02 = xz + wy;
    float r10 = xy + wz,        r11 = 1.0f - xx - zz, r12 = yz - wx;
    float r20 = xz - wy,        r21 = yz + wx,        r22 = 1.0f - xx - yy;

    // s_k^2 = exp(2 * raw_k)
    float s00 = __expf(2.0f * a0);
    float s11 = __expf(2.0f * a1);
    float s22 = __expf(2.0f * a2);

    float c00 = r00*r00*s00 + r01*r01*s11 + r02*r02*s22;
    float c01 = r00*r10*s00 + r01*r11*s11 + r02*r12*s22;
    float c02 = r00*r20*s00 + r01*r21*s11 + r02*r22*s22;
    float c11 = r10*r10*s00 + r11*r11*s11 + r12*r12*s22;
    float c12 = r10*r20*s00 + r11*r21*s11 + r12*r22*s22;
    float c22 = r20*r20*s00 + r21*r21*s11 + r22*r22*s22;

    // STS.32 stride-9: gcd(9,32)=1 -> conflict-free
    o[0] = c00; o[1] = c01; o[2] = c02;
    o[3] = c01; o[4] = c11; o[5] = c12;
    o[6] = c02; o[7] = c12; o[8] = c22;
}

__global__ __launch_bounds__(256)
void gaussian_cov_kernel(const float4* __restrict__ rot,
                         const float*  __restrict__ sc,
                         float*        __restrict__ out,
                         int n)
{
    __shared__ float sh_s[512 * 3];   //  6 KB staged scaling
    __shared__ float sh_o[512 * 9];   // 18 KB staged covariance

    const int tid  = threadIdx.x;
    const int base = blockIdx.x * 512;

    if (base + 512 <= n) {
        // ================= guardless fast path (all full blocks) =========

        // Front-batch all global reads: 2 quat LDG.128 + staged scaling.
        float4 q0 = __ldcs(&rot[base + tid]);
        float4 q1 = __ldcs(&rot[base + tid + 256]);

        {   // 1536 scaling floats = 384 float4, contiguous (3*base % 4 == 0)
            const float4* s4 = (const float4*)(sc + 3 * base);
            float4* sh4 = (float4*)sh_s;
            sh4[tid] = __ldcs(&s4[tid]);
            if (tid < 128) sh4[tid + 256] = __ldcs(&s4[tid + 256]);
        }
        __syncthreads();

        int l = tid;
        cov_one(q0, sh_s[3*l], sh_s[3*l+1], sh_s[3*l+2], sh_o + 9*l);
        l = tid + 256;
        cov_one(q1, sh_s[3*l], sh_s[3*l+1], sh_s[3*l+2], sh_o + 9*l);
        __syncthreads();

        // 4608 output floats = 1152 float4, contiguous (9*base % 4 == 0)
        float4* dst = (float4*)(out + 9 * base);
        const float4* src = (const float4*)sh_o;
        #pragma unroll
        for (int k = 0; k < 4; k++)
            __stcs(&dst[tid + 256 * k], src[tid + 256 * k]);
        if (tid < 128)
            __stcs(&dst[tid + 1024], src[tid + 1024]);
    } else {
        // ================= guarded tail path (last partial block) ========
        #pragma unroll
        for (int e = 0; e < 2; e++) {
            int i = base + tid + 256 * e;
            if (i < n) {
                float4 q = __ldg(&rot[i]);
                float c[9];
                cov_one(q, __ldg(sc + 3*i), __ldg(sc + 3*i + 1),
                        __ldg(sc + 3*i + 2), c);
                float* o = out + 9 * i;
                #pragma unroll
                for (int k = 0; k < 9; k++) o[k] = c[k];
            }
        }
    }
}

extern "C" void kernel_launch(void* const* d_in, const int* in_sizes, int n_in,
                              void* d_out, int out_size)
{
    const float4* rot = (const float4*)d_in[0];   // [N,4] float32
    const float*  sc  = (const float*) d_in[1];   // [N,3] float32
    float*        out = (float*)d_out;            // [N,3,3] float32

    int n  = in_sizes[0] / 4;
    int nb = (n + 511) / 512;
    gaussian_cov_kernel<<<nb, 256>>>(rot, sc, out, n);
}

// round 10
// speedup vs baseline: 1.0435x; 1.0007x over previous
#include <cuda_runtime.h>
#include <cuda_bf16.h>

// GaussianModel: cov = (R*diag(s)) (R*diag(s))^T per Gaussian, N=4M.
// Inputs: rotation_raw float32 [N,4], scaling_raw float32 [N,3]
// Output: cov float32 [N,3,3]
//
// R9: kernel was latency-limited (nothing saturated, issue=33%) with two
// block-wide barriers serializing load->compute->store across all 8 warps.
// Restructure into warp-autonomous 64-element tiles: warp-private smem
// slices, __syncwarp only, zero BAR.SYNC. Global patterns unchanged
// (all contiguous float4).

__device__ __forceinline__ void cov_one(float4 q, float a0, float a1, float a2,
                                        float* __restrict__ o /* 9 floats */)
{
    float w = q.x, x = q.y, y = q.z, z = q.w;

    // R is quadratic in the normalized quaternion: fold 2/||q||^2 into the
    // cross terms instead of normalizing.
    float n2   = w*w + x*x + y*y + z*z;
    float inv2 = __fdividef(2.0f, n2);

    float xx = x*x*inv2, yy = y*y*inv2, zz = z*z*inv2;
    float xy = x*y*inv2, xz = x*z*inv2, yz = y*z*inv2;
    float wx = w*x*inv2, wy = w*y*inv2, wz = w*z*inv2;

    float r00 = 1.0f - yy - zz, r01 = xy - wz,        r02 = xz + wy;
    float r10 = xy + wz,        r11 = 1.0f - xx - zz, r12 = yz - wx;
    float r20 = xz - wy,        r21 = yz + wx,        r22 = 1.0f - xx - yy;

    // s_k^2 = exp(2 * raw_k)
    float s00 = __expf(2.0f * a0);
    float s11 = __expf(2.0f * a1);
    float s22 = __expf(2.0f * a2);

    float c00 = r00*r00*s00 + r01*r01*s11 + r02*r02*s22;
    float c01 = r00*r10*s00 + r01*r11*s11 + r02*r12*s22;
    float c02 = r00*r20*s00 + r01*r21*s11 + r02*r22*s22;
    float c11 = r10*r10*s00 + r11*r11*s11 + r12*r12*s22;
    float c12 = r10*r20*s00 + r11*r21*s11 + r12*r22*s22;
    float c22 = r20*r20*s00 + r21*r21*s11 + r22*r22*s22;

    // STS.32 stride-9: gcd(9,32)=1 -> conflict-free
    o[0] = c00; o[1] = c01; o[2] = c02;
    o[3] = c01; o[4] = c11; o[5] = c12;
    o[6] = c02; o[7] = c12; o[8] = c22;
}

__global__ __launch_bounds__(256)
void gaussian_cov_kernel(const float4* __restrict__ rot,
                         const float*  __restrict__ sc,
                         float*        __restrict__ out,
                         int n)
{
    // Warp-private slices: 8 warps x (192 scale floats + 576 out floats)
    __shared__ float sh_s[8][192];   //  6 KB
    __shared__ float sh_o[8][576];   // 18 KB

    const int tid  = threadIdx.x;
    const int wrp  = tid >> 5;
    const int lane = tid & 31;
    const int base = blockIdx.x * 512;

    if (base + 512 <= n) {
        // ============ guardless warp-autonomous fast path ============
        const int eb = base + 64 * wrp;        // this warp's 64 elements

        // Quats: 2 contiguous LDG.128 per lane (4 lines/warp-instr, ideal)
        float4 q0 = __ldcs(&rot[eb + lane]);
        float4 q1 = __ldcs(&rot[eb + 32 + lane]);

        // Scales: 192 floats = 48 float4 at sc + 3*eb (3*eb % 4 == 0)
        {
            const float4* s4 = (const float4*)(sc + 3 * eb);
            float4* sh4 = (float4*)sh_s[wrp];
            sh4[lane] = __ldcs(&s4[lane]);
            if (lane < 16) sh4[32 + lane] = __ldcs(&s4[32 + lane]);
        }
        __syncwarp();

        const float* ss = sh_s[wrp];
        float*       so = sh_o[wrp];
        int l = lane;
        cov_one(q0, ss[3*l], ss[3*l+1], ss[3*l+2], so + 9*l);
        l = lane + 32;
        cov_one(q1, ss[3*l], ss[3*l+1], ss[3*l+2], so + 9*l);
        __syncwarp();

        // Out: 576 floats = 144 float4 contiguous at out + 9*eb
        float4* dst = (float4*)(out + 9 * eb);
        const float4* src = (const float4*)so;
        #pragma unroll
        for (int k = 0; k < 4; k++)
            __stcs(&dst[lane + 32 * k], src[lane + 32 * k]);
        if (lane < 16)
            __stcs(&dst[lane + 128], src[lane + 128]);
    } else {
        // ============ guarded tail path (last partial block) =========
        #pragma unroll
        for (int e = 0; e < 2; e++) {
            int i = base + tid + 256 * e;
            if (i < n) {
                float4 q = __ldg(&rot[i]);
                float c[9];
                cov_one(q, __ldg(sc + 3*i), __ldg(sc + 3*i + 1),
                        __ldg(sc + 3*i + 2), c);
                float* o = out + 9 * i;
                #pragma unroll
                for (int k = 0; k < 9; k++) o[k] = c[k];
            }
        }
    }
}

extern "C" void kernel_launch(void* const* d_in, const int* in_sizes, int n_in,
                              void* d_out, int out_size)
{
    const float4* rot = (const float4*)d_in[0];   // [N,4] float32
    const float*  sc  = (const float*) d_in[1];   // [N,3] float32
    float*        out = (float*)d_out;            // [N,3,3] float32

    int n  = in_sizes[0] / 4;
    int nb = (n + 511) / 512;
    gaussian_cov_kernel<<<nb, 256>>>(rot, sc, out, n);
}